// round 10
// baseline (speedup 1.0000x reference)
#include <cuda_runtime.h>
#include <cuda_bf16.h>

#define OUT_CH    128
#define MAX_EDGES 8192
#define THREADS   256
#define NBLK      296                     // <= guaranteed co-resident wave-1
#define WPB       (THREADS / 32)
#define NWARPS    (NBLK * WPB)            // 2368

// Packed per-edge histogram: count of token t in 16-bit field t of a u64.
// Zero at module load; phase 2 re-zeroes each entry after consuming it, so
// every launch (correctness run + each graph replay) starts from zeros.
__device__ unsigned long long g_hist[MAX_EDGES];
// Monotonic grid-barrier ticket (never reset; target derived per launch).
__device__ unsigned int g_ticket;

__device__ __forceinline__ void flush_group(const int4 t, const int4 s) {
    if (s.x == s.w) {                      // sorted -> whole int4 one segment
        const unsigned long long a =
              (1ull << ((t.x & 3) * 16)) + (1ull << ((t.y & 3) * 16))
            + (1ull << ((t.z & 3) * 16)) + (1ull << ((t.w & 3) * 16));
        if ((unsigned)s.x < MAX_EDGES) atomicAdd(&g_hist[s.x], a);
    } else {                               // rare: boundary inside the group
        const int ss[4] = {s.x, s.y, s.z, s.w};
        const int tt[4] = {t.x, t.y, t.z, t.w};
#pragma unroll
        for (int k = 0; k < 4; k++)
            if ((unsigned)ss[k] < MAX_EDGES)
                atomicAdd(&g_hist[ss[k]], 1ull << ((tt[k] & 3) * 16));
    }
}

__global__ void __launch_bounds__(THREADS)
fused_persistent(const int* __restrict__ tokens,
                 const int* __restrict__ segs,
                 const float* __restrict__ emb,   // [4][128]
                 float* __restrict__ out,         // [E][128]
                 int total_tokens,
                 int n_edges) {
    const int tid   = threadIdx.x;
    const int lane  = tid & 31;
    const int wid   = tid >> 5;
    const int gwarp = blockIdx.x * WPB + wid;

    // ================= Phase 1: streaming histogram =================
    const int4* tokens4 = (const int4*)tokens;
    const int4* segs4   = (const int4*)segs;
    const int n4      = total_tokens >> 2;
    const int nchunks = (n4 + 63) >> 6;          // 64 int4 per warp-chunk

    for (int c = gwarp; c < nchunks; c += NWARPS) {
        const int j1 = (c << 6) + lane;          // dense first half
        const int j2 = j1 + 32;                  // dense second half
        if (j2 < n4) {
            // 4 independent 16B loads, batched -> deep MLP, fully coalesced
            const int4 t1 = tokens4[j1];
            const int4 t2 = tokens4[j2];
            const int4 s1 = segs4[j1];
            const int4 s2 = segs4[j2];
            if (s1.x == s2.w) {                  // all 8 tokens one segment
                const unsigned long long a =
                      (1ull << ((t1.x & 3) * 16)) + (1ull << ((t1.y & 3) * 16))
                    + (1ull << ((t1.z & 3) * 16)) + (1ull << ((t1.w & 3) * 16))
                    + (1ull << ((t2.x & 3) * 16)) + (1ull << ((t2.y & 3) * 16))
                    + (1ull << ((t2.z & 3) * 16)) + (1ull << ((t2.w & 3) * 16));
                if ((unsigned)s1.x < MAX_EDGES) atomicAdd(&g_hist[s1.x], a);
            } else {
                flush_group(t1, s1);
                flush_group(t2, s2);
            }
        } else if (j1 < n4) {
            flush_group(tokens4[j1], segs4[j1]);
        }
    }
    // leftover tokens if T % 4 != 0 (not the case here; correctness insurance)
    if (blockIdx.x == 0 && tid == 0) {
        for (int i = n4 << 2; i < total_tokens; i++) {
            const int s = __ldg(&segs[i]);
            if ((unsigned)s < MAX_EDGES)
                atomicAdd(&g_hist[s], 1ull << ((__ldg(&tokens[i]) & 3) * 16));
        }
    }

    // ================= grid barrier (replay-safe, monotonic) =================
    __threadfence();                 // release this thread's REDs
    __syncthreads();                 // order all block threads before arrival
    if (tid == 0) {
        const unsigned t      = atomicAdd(&g_ticket, 1u);
        const unsigned target = (t / NBLK + 1u) * NBLK;
        while (*(volatile unsigned*)&g_ticket < target) __nanosleep(64);
        __threadfence();             // acquire
    }
    __syncthreads();

    // ================= Phase 2: hist -> output rows, reset hist =============
    const int d = lane * 4;
    const float4 e0v = *(const float4*)(emb + 0 * OUT_CH + d);
    const float4 e1v = *(const float4*)(emb + 1 * OUT_CH + d);
    const float4 e2v = *(const float4*)(emb + 2 * OUT_CH + d);
    const float4 e3v = *(const float4*)(emb + 3 * OUT_CH + d);

    for (int e = gwarp; e < n_edges; e += NWARPS) {
        unsigned long long h = 0ull;
        if (lane == 0) {
            h = *(volatile unsigned long long*)&g_hist[e];   // L2-coherent
            *(volatile unsigned long long*)&g_hist[e] = 0ull; // next replay
        }
        h = __shfl_sync(0xFFFFFFFFu, h, 0);

        const float f0 = (float)((unsigned)(h      ) & 0xFFFFu);
        const float f1 = (float)((unsigned)(h >> 16) & 0xFFFFu);
        const float f2 = (float)((unsigned)(h >> 32) & 0xFFFFu);
        const float f3 = (float)((unsigned)(h >> 48) & 0xFFFFu);
        const float inv = 1.0f / fmaxf(f0 + f1 + f2 + f3, 1.0f);

        float4 r;
        r.x = (f0 * e0v.x + f1 * e1v.x + f2 * e2v.x + f3 * e3v.x) * inv;
        r.y = (f0 * e0v.y + f1 * e1v.y + f2 * e2v.y + f3 * e3v.y) * inv;
        r.z = (f0 * e0v.z + f1 * e1v.z + f2 * e2v.z + f3 * e3v.z) * inv;
        r.w = (f0 * e0v.w + f1 * e1v.w + f2 * e2v.w + f3 * e3v.w) * inv;

        *(float4*)(out + (long long)e * OUT_CH + d) = r;
    }
}

extern "C" void kernel_launch(void* const* d_in, const int* in_sizes, int n_in,
                              void* d_out, int out_size) {
    // Inputs: 0 overlap_similarity f32[E], 1 overlap_length f32[E],
    //         2 tokens i32[T], 3 segment_ids i32[T], 4 embedding f32[4*128],
    //         5 n_edges
    const int*   tokens = (const int*)d_in[2];
    const int*   segs   = (const int*)d_in[3];
    const float* emb    = (const float*)d_in[4];
    float*       out    = (float*)d_out;

    const int total_tokens = in_sizes[2];
    const int n_edges      = out_size / OUT_CH;

    fused_persistent<<<NBLK, THREADS>>>(tokens, segs, emb, out,
                                        total_tokens, n_edges);
}

// round 11
// speedup vs baseline: 2.0250x; 2.0250x over previous
#include <cuda_runtime.h>
#include <cuda_bf16.h>

#define OUT_CH      128
#define TPB         256
#define TOK_PER_BLK 2048     // 8 tokens per thread
#define CAP         64       // owned edges handled per pass (ample; loop covers more)
#define EXT_CHUNK   1024     // extension chunk: one int4 per thread

// Block b owns tokens [2048b, 2048(b+1)) and, via two scalar probes, edges
// (segs[lo-1], segs[hi-1]]  (block 0 from edge 0; last block through E-1).
// This partitions all edges exactly for ANY sorted segs, empty edges included.
// The last owned edge may spill into the next window; a predicated extension
// scan finishes it. NO binary search anywhere.
__global__ void __launch_bounds__(TPB)
fused_edge_mean(const int* __restrict__ tokens,
                const int* __restrict__ segs,
                const float* __restrict__ emb,   // [4][128]
                float* __restrict__ out,         // [E][128]
                int T, int E) {
    __shared__ unsigned long long s_hist[CAP];
    __shared__ unsigned long long s_lut[256];
    __shared__ int s_eA, s_eB, s_cont;

    const int tid  = threadIdx.x;
    const int lane = tid & 31;
    const int wid  = tid >> 5;
    const int lo   = blockIdx.x * TOK_PER_BLK;
    if (lo >= T) return;
    const int hi = min(T, lo + TOK_PER_BLK);

    // ---- boundary probes: issued first, latency overlaps the main loads ----
    if (tid == 0)      s_eA = (lo == 0) ? 0 : (__ldg(&segs[lo - 1]) + 1);
    else if (tid == 1) s_eB = (hi >= T) ? (E - 1) : __ldg(&segs[hi - 1]);

    // ---- main loads: 8 contiguous tokens per thread (2 x int4 each array) ----
    const int4* tok4 = (const int4*)tokens;
    const int4* seg4 = (const int4*)segs;
    const int base = lo + tid * 8;
    const bool full = (base + 8 <= T);
    int4 sa, sb, ta, tb;
    if (full) {
        const int j = (lo >> 2) + tid * 2;
        sa = seg4[j]; sb = seg4[j + 1];
        ta = tok4[j]; tb = tok4[j + 1];
    }

    // LUT init while loads are in flight: entry i sums (1 << t*16) over its
    // four 2-bit fields t.
    {
        const int t0 = tid & 3, t1 = (tid >> 2) & 3,
                  t2 = (tid >> 4) & 3, t3 = (tid >> 6) & 3;
        s_lut[tid] = (1ull << (t0 * 16)) + (1ull << (t1 * 16))
                   + (1ull << (t2 * 16)) + (1ull << (t3 * 16));
    }
    __syncthreads();

    const int eA = s_eA;
    const int eB = s_eB;
    const int nown = eB - eA + 1;     // may be <=0 (interior block): loop skipped

    // embedding row slices (L1-hot, hoisted out of the pass loop)
    const int d = lane * 4;
    const float4 e0v = *(const float4*)(emb + 0 * OUT_CH + d);
    const float4 e1v = *(const float4*)(emb + 1 * OUT_CH + d);
    const float4 e2v = *(const float4*)(emb + 2 * OUT_CH + d);
    const float4 e3v = *(const float4*)(emb + 3 * OUT_CH + d);

    for (int cbase = 0; cbase < nown; cbase += CAP) {   // one pass normally
        const int fA = eA + cbase;
        const int fB = min(eB, fA + CAP - 1);

        if (tid < CAP) s_hist[tid] = 0ull;
        __syncthreads();

        // ---- main accumulation over this block's token window ----
        if (full) {
            if (sa.x == sb.w) {                 // all 8 tokens in one segment
                if ((unsigned)(sa.x - fA) <= (unsigned)(fB - fA)) {
                    const int ia = (ta.x & 3) | ((ta.y & 3) << 2)
                                 | ((ta.z & 3) << 4) | ((ta.w & 3) << 6);
                    const int ib = (tb.x & 3) | ((tb.y & 3) << 2)
                                 | ((tb.z & 3) << 4) | ((tb.w & 3) << 6);
                    atomicAdd(&s_hist[sa.x - fA], s_lut[ia] + s_lut[ib]);
                }
            } else {                            // segment boundary in strip
                const int ss[8] = {sa.x, sa.y, sa.z, sa.w, sb.x, sb.y, sb.z, sb.w};
                const int tt[8] = {ta.x, ta.y, ta.z, ta.w, tb.x, tb.y, tb.z, tb.w};
                int cur = ss[0];
                unsigned long long acc = 0ull;
#pragma unroll
                for (int k = 0; k < 8; k++) {
                    if (ss[k] != cur) {
                        if (acc && (unsigned)(cur - fA) <= (unsigned)(fB - fA))
                            atomicAdd(&s_hist[cur - fA], acc);
                        cur = ss[k]; acc = 0ull;
                    }
                    acc += 1ull << ((tt[k] & 3) * 16);
                }
                if (acc && (unsigned)(cur - fA) <= (unsigned)(fB - fA))
                    atomicAdd(&s_hist[cur - fA], acc);
            }
        } else if (base < T) {                  // ragged tail (insurance)
            for (int k = 0; k < 8 && base + k < T; k++) {
                const int s = __ldg(&segs[base + k]);
                if ((unsigned)(s - fA) <= (unsigned)(fB - fA))
                    atomicAdd(&s_hist[s - fA],
                              1ull << ((__ldg(&tokens[base + k]) & 3) * 16));
            }
        }

        // ---- extension: finish edge eB's spill into following windows ----
        if (fB == eB && hi < T) {
            int extb = hi;
            bool more = true;
            while (more) {
                if (tid == 0) s_cont = 0;
                __syncthreads();
                const int b2 = extb + tid * 4;
                if (b2 < T) {
                    const int j = (extb >> 2) + tid;
                    const int4 s4 = seg4[j];
                    const bool anyeq = (s4.x == eB) | (s4.y == eB)
                                     | (s4.z == eB) | (s4.w == eB);
                    if (anyeq) {
                        const int4 t4 = tok4[j];
                        const int ssx[4] = {s4.x, s4.y, s4.z, s4.w};
                        const int ttx[4] = {t4.x, t4.y, t4.z, t4.w};
                        unsigned long long acc = 0ull;
#pragma unroll
                        for (int k = 0; k < 4; k++)
                            if (b2 + k < T && ssx[k] == eB)
                                acc += 1ull << ((ttx[k] & 3) * 16);
                        if (acc) atomicAdd(&s_hist[eB - fA], acc);
                    }
                    // continuation: thread holding the chunk's last token
                    const int tlast = min(T, extb + EXT_CHUNK) - 1;
                    if (tlast >= b2 && tlast < b2 + 4) {
                        const int sl = (tlast == b2)     ? s4.x
                                     : (tlast == b2 + 1) ? s4.y
                                     : (tlast == b2 + 2) ? s4.z : s4.w;
                        if (sl == eB && extb + EXT_CHUNK < T) s_cont = 1;
                    }
                }
                __syncthreads();
                more = (s_cont != 0);
                extb += EXT_CHUNK;
            }
        }
        __syncthreads();

        // ---- epilogue: write rows [fA, fB], one warp per row (strided) ----
        const int nrows = fB - fA + 1;
        for (int le = wid; le < nrows; le += TPB / 32) {
            const int e = fA + le;
            if (e >= E) break;
            const unsigned long long h = s_hist[le];
            const float f0 = (float)((unsigned)(h      ) & 0xFFFFu);
            const float f1 = (float)((unsigned)(h >> 16) & 0xFFFFu);
            const float f2 = (float)((unsigned)(h >> 32) & 0xFFFFu);
            const float f3 = (float)((unsigned)(h >> 48) & 0xFFFFu);
            const float inv = 1.0f / fmaxf(f0 + f1 + f2 + f3, 1.0f);

            float4 r;
            r.x = (f0 * e0v.x + f1 * e1v.x + f2 * e2v.x + f3 * e3v.x) * inv;
            r.y = (f0 * e0v.y + f1 * e1v.y + f2 * e2v.y + f3 * e3v.y) * inv;
            r.z = (f0 * e0v.z + f1 * e1v.z + f2 * e2v.z + f3 * e3v.z) * inv;
            r.w = (f0 * e0v.w + f1 * e1v.w + f2 * e2v.w + f3 * e3v.w) * inv;

            *(float4*)(out + (long long)e * OUT_CH + d) = r;
        }
        __syncthreads();   // hist reuse guard for (pathological) extra passes
    }
}

extern "C" void kernel_launch(void* const* d_in, const int* in_sizes, int n_in,
                              void* d_out, int out_size) {
    // Inputs: 0 overlap_similarity f32[E], 1 overlap_length f32[E],
    //         2 tokens i32[T], 3 segment_ids i32[T], 4 embedding f32[4*128],
    //         5 n_edges
    const int*   tokens = (const int*)d_in[2];
    const int*   segs   = (const int*)d_in[3];
    const float* emb    = (const float*)d_in[4];
    float*       out    = (float*)d_out;

    const int T = in_sizes[2];
    const int E = out_size / OUT_CH;

    const int blocks = (T + TOK_PER_BLK - 1) / TOK_PER_BLK;   // 1024
    fused_edge_mean<<<blocks, TPB>>>(tokens, segs, emb, out, T, E);
}

// round 12
// speedup vs baseline: 2.4179x; 1.1940x over previous
#include <cuda_runtime.h>
#include <cuda_bf16.h>

#define OUT_CH 128
#define TPB    256
#define TOKB   2048     // tokens per block (8 per thread)
#define CAP    32       // owned edges per pass (loop covers pathological cases)

// Block b owns tokens [2048b, 2048b+2048) and edges (segs[lo-1], segs[hi-1]]
// (block 0 from 0; last block through E-1): an exact edge partition for ANY
// sorted segs, empty edges included. The tail edge may spill into following
// windows; warp 0 finishes it with a ballot-controlled scan (no block syncs).
// No binary search anywhere; O(1) boundary probes.
__global__ void __launch_bounds__(TPB, 6)
fused_edge_mean(const int* __restrict__ tokens,
                const int* __restrict__ segs,
                const float* __restrict__ emb,   // [4][128]
                float* __restrict__ out,         // [E][128]
                int T, int E) {
    __shared__ unsigned long long s_hist[CAP];
    __shared__ unsigned long long s_lut[256];
    __shared__ int s_eA, s_eB;

    const int tid  = threadIdx.x;
    const int lane = tid & 31;
    const int wid  = tid >> 5;
    const int lo   = blockIdx.x * TOKB;
    if (lo >= T) return;
    const int hi = min(T, lo + TOKB);

    // ---- O(1) boundary probes (latency overlaps the stream loads) ----
    if (tid == 0) s_eA = (lo == 0) ? 0 : (__ldg(&segs[lo - 1]) + 1);
    if (tid == 1) s_eB = (hi >= T) ? (E - 1) : __ldg(&segs[hi - 1]);

    // ---- stream loads: 8 contiguous tokens/thread, 4 x LDG.128 batched ----
    const int4* tok4 = (const int4*)tokens;
    const int4* seg4 = (const int4*)segs;
    const int j    = (lo >> 2) + tid * 2;
    const int base = lo + tid * 8;
    const bool full = (base + 8 <= T);
    int4 sa, sb;
    unsigned pk = 0;                        // 8 tokens, 2 bits each
    if (full) {
        sa = seg4[j]; sb = seg4[j + 1];
        const int4 ta = tok4[j], tb = tok4[j + 1];
        pk = (ta.x & 3)        | ((ta.y & 3) << 2)
           | ((ta.z & 3) << 4) | ((ta.w & 3) << 6)
           | ((tb.x & 3) << 8) | ((tb.y & 3) << 10)
           | ((tb.z & 3) << 12)| ((tb.w & 3) << 14);
    }

    // LUT while loads fly: entry i = sum over its four 2-bit fields t of 1<<(t*16)
    {
        const int t0 = tid & 3, t1 = (tid >> 2) & 3,
                  t2 = (tid >> 4) & 3, t3 = (tid >> 6) & 3;
        s_lut[tid] = (1ull << (t0 * 16)) + (1ull << (t1 * 16))
                   + (1ull << (t2 * 16)) + (1ull << (t3 * 16));
    }
    if (tid < CAP) s_hist[tid] = 0ull;
    __syncthreads();

    const int eA = s_eA, eB = s_eB;
    const int nown = eB - eA + 1;           // uniform across block (may be <=0)

    for (int cbase = 0; cbase < nown; cbase += CAP) {
        const int fA = eA + cbase;
        const int fB = min(eB, fA + CAP - 1);
        const unsigned span = (unsigned)(fB - fA);

        // ---- accumulate this thread's strip ----
        if (full) {
            const int s0 = sa.x;
            unsigned long long accH;            // head-run partial (keyed s0)
            if (s0 == sb.w) {                   // uniform strip (~97%)
                accH = s_lut[pk & 0xFF] + s_lut[(pk >> 8) & 0xFF];
            } else {                            // boundary strip
                accH = 0ull;
                unsigned long long run = 0ull;
                int cur = s0; bool head = true;
#define DOK(SK, K)                                                          \
                do {                                                        \
                    if ((SK) != cur) {                                      \
                        if (head) { accH = run; head = false; }             \
                        else if (run && (unsigned)(cur - fA) <= span)       \
                            atomicAdd(&s_hist[cur - fA], run);              \
                        run = 0ull; cur = (SK);                             \
                    }                                                       \
                    run += 1ull << (((pk >> (2 * (K))) & 3) * 16);          \
                } while (0)
                DOK(sa.x, 0); DOK(sa.y, 1); DOK(sa.z, 2); DOK(sa.w, 3);
                DOK(sb.x, 4); DOK(sb.y, 5); DOK(sb.z, 6); DOK(sb.w, 7);
#undef DOK
                if (head) accH = run;
                else if (run && (unsigned)(cur - fA) <= span)
                    atomicAdd(&s_hist[cur - fA], run);
            }
            // warp-segmented suffix reduction on monotone key s0
            int le = s0;
#pragma unroll
            for (int off = 1; off < 32; off <<= 1) {
                const unsigned long long v = __shfl_down_sync(0xFFFFFFFFu, accH, off);
                const int l2 = __shfl_down_sync(0xFFFFFFFFu, le, off);
                if (lane + off < 32 && l2 == le) accH += v;
            }
            const int prev = __shfl_up_sync(0xFFFFFFFFu, le, 1);
            if ((lane == 0 || prev != le) && accH &&
                (unsigned)(le - fA) <= span)
                atomicAdd(&s_hist[le - fA], accH);
        } else if (base < T) {                  // ragged tail insurance
            for (int k = 0; k < 8 && base + k < T; k++) {
                const int s = __ldg(&segs[base + k]);
                if ((unsigned)(s - fA) <= span)
                    atomicAdd(&s_hist[s - fA],
                              1ull << ((__ldg(&tokens[base + k]) & 3) * 16));
            }
        }
        __syncthreads();

        // ---- epilogue ----
        const int d = lane * 4;
        const int lastInt = (fB == eB) ? eB - 1 : fB;   // warp0 owns eB row

        if (wid > 0) {
            for (int e = fA + (wid - 1); e <= lastInt; e += 7) {
                const unsigned long long h = s_hist[e - fA];
                const float f0 = (float)((unsigned)(h      ) & 0xFFFFu);
                const float f1 = (float)((unsigned)(h >> 16) & 0xFFFFu);
                const float f2 = (float)((unsigned)(h >> 32) & 0xFFFFu);
                const float f3 = (float)((unsigned)(h >> 48) & 0xFFFFu);
                const float inv = 1.0f / fmaxf(f0 + f1 + f2 + f3, 1.0f);
                float4 r;
                const float4 v0 = *(const float4*)(emb + 0 * OUT_CH + d);
                const float4 v1 = *(const float4*)(emb + 1 * OUT_CH + d);
                const float4 v2 = *(const float4*)(emb + 2 * OUT_CH + d);
                const float4 v3 = *(const float4*)(emb + 3 * OUT_CH + d);
                r.x = (f0 * v0.x + f1 * v1.x + f2 * v2.x + f3 * v3.x) * inv;
                r.y = (f0 * v0.y + f1 * v1.y + f2 * v2.y + f3 * v3.y) * inv;
                r.z = (f0 * v0.z + f1 * v1.z + f2 * v2.z + f3 * v3.z) * inv;
                r.w = (f0 * v0.w + f1 * v1.w + f2 * v2.w + f3 * v3.w) * inv;
                *(float4*)(out + (long long)e * OUT_CH + d) = r;
            }
        } else if (fB == eB) {
            // warp 0: finish the spilling tail edge, then write its row
            unsigned long long ext = 0ull;
            int pos = hi;
            while (pos < T) {
                const int jj  = (pos >> 2) + lane;
                const int tb0 = pos + lane * 4;
                int4 s4 = make_int4(-1, -1, -1, -1), t4;
                if (tb0 < T) {
                    s4 = seg4[jj]; t4 = tok4[jj];
                    if (s4.x == eB)               ext += 1ull << ((t4.x & 3) * 16);
                    if (tb0 + 1 < T && s4.y == eB) ext += 1ull << ((t4.y & 3) * 16);
                    if (tb0 + 2 < T && s4.z == eB) ext += 1ull << ((t4.z & 3) * 16);
                    if (tb0 + 3 < T && s4.w == eB) ext += 1ull << ((t4.w & 3) * 16);
                }
                // continue only if the chunk's last in-bounds token is still eB
                const int lastIdx  = min(T, pos + 128) - 1;
                const int lastLane = (lastIdx - pos) >> 2;
                int sl = -1;
                if (lane == lastLane && tb0 < T) {
                    const int rix = lastIdx - tb0;
                    sl = (rix == 0) ? s4.x : (rix == 1) ? s4.y
                       : (rix == 2) ? s4.z : s4.w;
                }
                sl = __shfl_sync(0xFFFFFFFFu, sl, lastLane);
                pos += 128;
                if (sl != eB) break;
            }
            const unsigned xlo = __reduce_add_sync(0xFFFFFFFFu, (unsigned)ext);
            const unsigned xhi = __reduce_add_sync(0xFFFFFFFFu, (unsigned)(ext >> 32));

            const unsigned long long h = s_hist[eB - fA];
            const float f0 = (float)(((unsigned)(h      ) & 0xFFFFu) + (xlo & 0xFFFFu));
            const float f1 = (float)(((unsigned)(h >> 16) & 0xFFFFu) + (xlo >> 16));
            const float f2 = (float)(((unsigned)(h >> 32) & 0xFFFFu) + (xhi & 0xFFFFu));
            const float f3 = (float)(((unsigned)(h >> 48) & 0xFFFFu) + (xhi >> 16));
            const float inv = 1.0f / fmaxf(f0 + f1 + f2 + f3, 1.0f);
            float4 r;
            const float4 v0 = *(const float4*)(emb + 0 * OUT_CH + d);
            const float4 v1 = *(const float4*)(emb + 1 * OUT_CH + d);
            const float4 v2 = *(const float4*)(emb + 2 * OUT_CH + d);
            const float4 v3 = *(const float4*)(emb + 3 * OUT_CH + d);
            r.x = (f0 * v0.x + f1 * v1.x + f2 * v2.x + f3 * v3.x) * inv;
            r.y = (f0 * v0.y + f1 * v1.y + f2 * v2.y + f3 * v3.y) * inv;
            r.z = (f0 * v0.z + f1 * v1.z + f2 * v2.z + f3 * v3.z) * inv;
            r.w = (f0 * v0.w + f1 * v1.w + f2 * v2.w + f3 * v3.w) * inv;
            *(float4*)(out + (long long)eB * OUT_CH + d) = r;
        }

        if (cbase + CAP < nown) {       // pathological multi-pass only
            __syncthreads();
            if (tid < CAP) s_hist[tid] = 0ull;
            __syncthreads();
        }
    }
}

extern "C" void kernel_launch(void* const* d_in, const int* in_sizes, int n_in,
                              void* d_out, int out_size) {
    // Inputs: 0 overlap_similarity f32[E], 1 overlap_length f32[E],
    //         2 tokens i32[T], 3 segment_ids i32[T], 4 embedding f32[4*128],
    //         5 n_edges
    const int*   tokens = (const int*)d_in[2];
    const int*   segs   = (const int*)d_in[3];
    const float* emb    = (const float*)d_in[4];
    float*       out    = (float*)d_out;

    const int T = in_sizes[2];
    const int E = out_size / OUT_CH;

    const int blocks = (T + TOKB - 1) / TOKB;   // 1024
    fused_edge_mean<<<blocks, TPB>>>(tokens, segs, emb, out, T, E);
}

// round 13
// speedup vs baseline: 3.8571x; 1.5952x over previous
#include <cuda_runtime.h>
#include <cuda_bf16.h>

#define OUT_CH 128
#define TPB    256
#define TOKB   2048     // tokens per block, 8 per thread
#define CAP    16       // owned edges per pass (multi-pass covers pathology)
#define NSUB   8        // sub-slots per edge (spread same-address atomics)

// Block b owns tokens [2048b, 2048b+2048) and edges (segs[lo-1], segs[hi-1]]
// (block 0 from 0; last block through E-1): exact edge partition for ANY
// sorted segs, empty edges included. Tail edge eB may spill into following
// windows; warp 0 finishes it with a ballot/shfl-controlled scan.
// No binary search. Deposits: ONE sub-slotted smem atomic per thread.
__global__ void __launch_bounds__(TPB)
fused_edge_mean(const int* __restrict__ tokens,
                const int* __restrict__ segs,
                const float* __restrict__ emb,   // [4][128]
                float* __restrict__ out,         // [E][128]
                int T, int E) {
    __shared__ unsigned long long s_hist[CAP][NSUB];   // 1 KB
    __shared__ unsigned long long s_lut[256];          // 2 KB
    __shared__ int s_eA, s_eB;

    const int tid  = threadIdx.x;
    const int lane = tid & 31;
    const int wid  = tid >> 5;
    const int lo   = blockIdx.x * TOKB;
    if (lo >= T) return;
    const int hi = min(T, lo + TOKB);

    // ---- O(1) ownership probes (two warps, overlap the stream loads) ----
    if (tid == 0)  s_eA = (lo == 0) ? 0 : (__ldg(&segs[lo - 1]) + 1);
    if (tid == 32) s_eB = (hi >= T) ? (E - 1) : __ldg(&segs[hi - 1]);

    // ---- stream loads: 8 contiguous tokens/thread + strip end-probes ----
    const int4* tok4 = (const int4*)tokens;
    const int4* seg4 = (const int4*)segs;
    const int base = lo + tid * 8;
    const int j    = base >> 2;
    const bool full = (base + 8 <= T);
    int4 ta, tb;
    int sfirst = 0, slast = -1;
    if (full) {
        ta = tok4[j]; tb = tok4[j + 1];
        sfirst = __ldg(&segs[base]);        // same 32B sectors as the strip
        slast  = __ldg(&segs[base + 7]);
    }

    // LUT + hist zero while loads are in flight.
    // s_lut[i] = sum over i's four 2-bit fields t of (1 << t*16)
    {
        const int t0 = tid & 3, t1 = (tid >> 2) & 3,
                  t2 = (tid >> 4) & 3, t3 = (tid >> 6) & 3;
        s_lut[tid] = (1ull << (t0 * 16)) + (1ull << (t1 * 16))
                   + (1ull << (t2 * 16)) + (1ull << (t3 * 16));
    }
    if (tid < CAP * NSUB) ((unsigned long long*)s_hist)[tid] = 0ull;
    __syncthreads();

    const int eA = s_eA, eB = s_eB;
    const int nown = eB - eA + 1;           // may be <=0: block writes nothing

    // 16-bit token pack (2 bits per token); survives the pass loop
    unsigned pk = 0;
    if (full)
        pk = (ta.x & 3)         | ((ta.y & 3) << 2)
           | ((ta.z & 3) << 4)  | ((ta.w & 3) << 6)
           | ((tb.x & 3) << 8)  | ((tb.y & 3) << 10)
           | ((tb.z & 3) << 12) | ((tb.w & 3) << 14);

    for (int cbase = 0; cbase < nown; cbase += CAP) {   // one pass normally
        const int fA = eA + cbase;
        const int fB = min(eB, fA + CAP - 1);
        const unsigned span = (unsigned)(fB - fA);

        // ---- deposit this thread's strip ----
        if (full) {
            if (sfirst == slast) {          // uniform strip (~97%)
                const int le = sfirst - fA;
                if ((unsigned)le <= span)
                    atomicAdd(&s_hist[le][lane & (NSUB - 1)],
                              s_lut[pk & 0xFF] + s_lut[(pk >> 8) & 0xFF]);
            } else {                        // boundary strip: walk runs
                const int4 sa = seg4[j], sb = seg4[j + 1];   // L1 hits
                int cur = sa.x;
                unsigned long long run = 0ull;
#define DEP(C, R)                                                           \
                do {                                                        \
                    const int _le = (C) - fA;                               \
                    if ((R) && (unsigned)_le <= span)                       \
                        atomicAdd(&s_hist[_le][lane & (NSUB - 1)], (R));    \
                } while (0)
#define DOK(SK, K)                                                          \
                do {                                                        \
                    if ((SK) != cur) { DEP(cur, run); run = 0ull; cur = (SK); } \
                    run += 1ull << (((pk >> (2 * (K))) & 3) * 16);          \
                } while (0)
                DOK(sa.x, 0); DOK(sa.y, 1); DOK(sa.z, 2); DOK(sa.w, 3);
                DOK(sb.x, 4); DOK(sb.y, 5); DOK(sb.z, 6); DOK(sb.w, 7);
                DEP(cur, run);
#undef DOK
            }
        } else if (base < T) {              // ragged tail insurance
            for (int k = 0; k < 8 && base + k < T; k++) {
                const int s = __ldg(&segs[base + k]);
                const int le = s - fA;
                if ((unsigned)le <= span)
                    atomicAdd(&s_hist[le][lane & (NSUB - 1)],
                              1ull << ((__ldg(&tokens[base + k]) & 3) * 16));
            }
        }
        __syncthreads();

        // ---- epilogue ----
        const int d = lane * 4;
        const bool tailPass = (fB == eB);
        const int lastInt = tailPass ? fB - 1 : fB;   // warp 0 owns eB's row

        if (wid > 0 || !tailPass) {
            const int stride = tailPass ? 7 : 8;
            const int first  = tailPass ? fA + (wid - 1) : fA + wid;
            for (int e = first; e <= lastInt; e += stride) {
                const int le = e - fA;
                unsigned long long h = 0ull;
#pragma unroll
                for (int q = 0; q < NSUB; q++) h += s_hist[le][q];

                const float f0 = (float)((unsigned)(h      ) & 0xFFFFu);
                const float f1 = (float)((unsigned)(h >> 16) & 0xFFFFu);
                const float f2 = (float)((unsigned)(h >> 32) & 0xFFFFu);
                const float f3 = (float)((unsigned)(h >> 48) & 0xFFFFu);
                const float inv = 1.0f / fmaxf(f0 + f1 + f2 + f3, 1.0f);

                const float4 v0 = *(const float4*)(emb + 0 * OUT_CH + d);
                const float4 v1 = *(const float4*)(emb + 1 * OUT_CH + d);
                const float4 v2 = *(const float4*)(emb + 2 * OUT_CH + d);
                const float4 v3 = *(const float4*)(emb + 3 * OUT_CH + d);
                float4 r;
                r.x = (f0 * v0.x + f1 * v1.x + f2 * v2.x + f3 * v3.x) * inv;
                r.y = (f0 * v0.y + f1 * v1.y + f2 * v2.y + f3 * v3.y) * inv;
                r.z = (f0 * v0.z + f1 * v1.z + f2 * v2.z + f3 * v3.z) * inv;
                r.w = (f0 * v0.w + f1 * v1.w + f2 * v2.w + f3 * v3.w) * inv;
                *(float4*)(out + (long long)e * OUT_CH + d) = r;
            }
        }

        if (wid == 0 && tailPass) {
            // finish eB's spill into following windows, then write its row
            unsigned long long ext = 0ull;
            int pos = hi;
            while (pos < T) {
                const int idx = pos + lane * 4;
                int4 s4 = make_int4(-1, -1, -1, -1), t4;
                if (idx < T) {
                    const int jj = (pos >> 2) + lane;
                    s4 = seg4[jj]; t4 = tok4[jj];
                    if (s4.x == eB)                ext += 1ull << ((t4.x & 3) * 16);
                    if (idx + 1 < T && s4.y == eB) ext += 1ull << ((t4.y & 3) * 16);
                    if (idx + 2 < T && s4.z == eB) ext += 1ull << ((t4.z & 3) * 16);
                    if (idx + 3 < T && s4.w == eB) ext += 1ull << ((t4.w & 3) * 16);
                }
                const int lastIdx  = min(T, pos + 128) - 1;
                const int lastLane = (lastIdx - pos) >> 2;
                int sl = -1;
                if (lane == lastLane) {
                    const int rix = lastIdx - idx;
                    sl = (rix == 0) ? s4.x : (rix == 1) ? s4.y
                       : (rix == 2) ? s4.z : s4.w;
                }
                sl = __shfl_sync(0xFFFFFFFFu, sl, lastLane);
                pos += 128;
                if (sl != eB) break;
            }
            const unsigned xlo = __reduce_add_sync(0xFFFFFFFFu, (unsigned)ext);
            const unsigned xhi = __reduce_add_sync(0xFFFFFFFFu, (unsigned)(ext >> 32));

            unsigned long long h = 0ull;
#pragma unroll
            for (int q = 0; q < NSUB; q++) h += s_hist[eB - fA][q];

            const float f0 = (float)(((unsigned)(h      ) & 0xFFFFu) + (xlo & 0xFFFFu));
            const float f1 = (float)(((unsigned)(h >> 16) & 0xFFFFu) + (xlo >> 16));
            const float f2 = (float)(((unsigned)(h >> 32) & 0xFFFFu) + (xhi & 0xFFFFu));
            const float f3 = (float)(((unsigned)(h >> 48) & 0xFFFFu) + (xhi >> 16));
            const float inv = 1.0f / fmaxf(f0 + f1 + f2 + f3, 1.0f);

            const float4 v0 = *(const float4*)(emb + 0 * OUT_CH + d);
            const float4 v1 = *(const float4*)(emb + 1 * OUT_CH + d);
            const float4 v2 = *(const float4*)(emb + 2 * OUT_CH + d);
            const float4 v3 = *(const float4*)(emb + 3 * OUT_CH + d);
            float4 r;
            r.x = (f0 * v0.x + f1 * v1.x + f2 * v2.x + f3 * v3.x) * inv;
            r.y = (f0 * v0.y + f1 * v1.y + f2 * v2.y + f3 * v3.y) * inv;
            r.z = (f0 * v0.z + f1 * v1.z + f2 * v2.z + f3 * v3.z) * inv;
            r.w = (f0 * v0.w + f1 * v1.w + f2 * v2.w + f3 * v3.w) * inv;
            *(float4*)(out + (long long)eB * OUT_CH + d) = r;
        }

        if (cbase + CAP < nown) {       // pathological multi-pass only
            __syncthreads();
            if (tid < CAP * NSUB) ((unsigned long long*)s_hist)[tid] = 0ull;
            __syncthreads();
        }
    }
}

extern "C" void kernel_launch(void* const* d_in, const int* in_sizes, int n_in,
                              void* d_out, int out_size) {
    // Inputs: 0 overlap_similarity f32[E], 1 overlap_length f32[E],
    //         2 tokens i32[T], 3 segment_ids i32[T], 4 embedding f32[4*128],
    //         5 n_edges
    const int*   tokens = (const int*)d_in[2];
    const int*   segs   = (const int*)d_in[3];
    const float* emb    = (const float*)d_in[4];
    float*       out    = (float*)d_out;

    const int T = in_sizes[2];
    const int E = out_size / OUT_CH;

    const int blocks = (T + TOKB - 1) / TOKB;   // 1024
    fused_edge_mean<<<blocks, TPB>>>(tokens, segs, emb, out, T, E);
}